// round 15
// baseline (speedup 1.0000x reference)
#include <cuda_runtime.h>
#include <cstdint>

#define HF 128
#define WF 192
#define NA 9
#define HW (HF*WF)               // 24576
#define NTOT (HW*NA)             // 221184
#define TOPN 6000
#define POSTN 300
#define NB 94                    // ceil(6000/64) (sup words)
#define CAND_MAX 16384
#define RTOP 1024                // early-NMS rank bound
#define RW 16                    // RTOP/64 words per row
#define RT 16                    // RTOP/64 tiles per side
#define NTILE (RT*(RT+1)/2)      // 136 triangular tiles
#define NBLK NTILE               // fused-kernel blocks (co-resident: 136 <= 148 SMs)
#define FTH 256                  // fused-kernel threads per block

__constant__ float c_anchors[NA][4] = {
    {-84.f,  -40.f,  99.f,  55.f},
    {-176.f, -88.f,  191.f, 103.f},
    {-360.f, -184.f, 375.f, 199.f},
    {-56.f,  -56.f,  71.f,  71.f},
    {-120.f, -120.f, 135.f, 135.f},
    {-248.f, -248.f, 263.f, 263.f},
    {-36.f,  -80.f,  51.f,  95.f},
    {-80.f,  -168.f, 95.f,  183.f},
    {-168.f, -344.f, 183.f, 359.f}
};

// single zeroed region (one memset node)
struct ZeroBlock {
    unsigned int hist[65536];
    unsigned long long sup[NB];
};
__device__ __align__(16) ZeroBlock g_z;

__device__ unsigned int g_srt[NTOT];                 // 32-bit sortable score
__device__ float4 g_boxes[NTOT];                     // t = a*HW + k
__device__ __align__(16) unsigned int g_sfx[65536];  // sfx[b] = #keys in buckets > b
__device__ unsigned int g_thresh;
__device__ unsigned int g_cand_count;
__device__ __align__(16) unsigned long long g_cand[CAND_MAX];
__device__ float4 g_top_boxes[TOPN];
__device__ __align__(16) unsigned long long g_maskR[RTOP * RW];   // early mask

// software grid barrier state (self-resetting across replays:
// count returns to 0 after each release; gen is monotonic)
__device__ unsigned int g_bar_count;
__device__ unsigned int g_bar_gen;

__device__ __forceinline__ void grid_bar() {
    __threadfence();
    __syncthreads();
    if (threadIdx.x == 0) {
        unsigned int gen = atomicAdd(&g_bar_gen, 0u);
        if (atomicAdd(&g_bar_count, 1u) == NBLK - 1) {
            g_bar_count = 0;
            __threadfence();
            atomicAdd(&g_bar_gen, 1u);
        } else {
            while (atomicAdd(&g_bar_gen, 0u) == gen) { __nanosleep(64); }
        }
    }
    __syncthreads();
    __threadfence();
}

__device__ __forceinline__ void cp_async16(void* smem_dst, const void* gmem_src) {
    unsigned int d = (unsigned int)__cvta_generic_to_shared(smem_dst);
    asm volatile("cp.async.cg.shared.global [%0], [%1], 16;" :: "r"(d), "l"(gmem_src) : "memory");
}
__device__ __forceinline__ void cp_async_commit() {
    asm volatile("cp.async.commit_group;" ::: "memory");
}
__device__ __forceinline__ void cp_async_wait0() {
    asm volatile("cp.async.wait_group 0;" ::: "memory");
}

// ---------------- K1: decode + boxes + sortable score + histogram ----------------
__global__ void k_score_box(const float* __restrict__ scores,
                            const float* __restrict__ deltas,
                            const float* __restrict__ im_info) {
    int t = blockIdx.x * blockDim.x + threadIdx.x;
    if (t >= NTOT) return;
    int a = t / HW;
    int k = t - a * HW;
    int xs = k >> 7;          // meshgrid 'ij' quirk: shift row k -> (x=k/128, y=k%128)
    int ys = k & 127;

    float sc = scores[(NA + a) * HW + k];
    float dx = deltas[(4*a + 0) * HW + k];
    float dy = deltas[(4*a + 1) * HW + k];
    float dw = deltas[(4*a + 2) * HW + k];
    float dh = deltas[(4*a + 3) * HW + k];

    float sx = 16.f * (float)xs;
    float sy = 16.f * (float)ys;
    float ax1 = c_anchors[a][0] + sx;
    float ay1 = c_anchors[a][1] + sy;
    float ax2 = c_anchors[a][2] + sx;
    float ay2 = c_anchors[a][3] + sy;

    float w = ax2 - ax1 + 1.f;
    float h = ay2 - ay1 + 1.f;
    float cx = ax1 + 0.5f * w;
    float cy = ay1 + 0.5f * h;

    float pcx = dx * w + cx;
    float pcy = dy * h + cy;
    float pw = expf(dw) * w;
    float ph = expf(dh) * h;

    float x1 = pcx - 0.5f * pw;
    float y1 = pcy - 0.5f * ph;
    float x2 = pcx + 0.5f * pw;
    float y2 = pcy + 0.5f * ph;

    float im0 = im_info[0], im1 = im_info[1], im2 = im_info[2];
    x1 = fminf(fmaxf(x1, 0.f), im1 - 1.f);
    x2 = fminf(fmaxf(x2, 0.f), im1 - 1.f);
    y1 = fminf(fmaxf(y1, 0.f), im0 - 1.f);
    y2 = fminf(fmaxf(y2, 0.f), im0 - 1.f);

    float ms = 16.f * im2;
    bool valid = (x2 - x1 + 1.f >= ms) && (y2 - y1 + 1.f >= ms);

    unsigned int srt;
    if (valid) {
        unsigned int b = __float_as_uint(sc);
        srt = (b & 0x80000000u) ? ~b : (b | 0x80000000u);
    } else {
        srt = 0x007FFFFFu;   // flip(-inf)
    }
    g_srt[t] = srt;
    g_boxes[t] = make_float4(x1, y1, x2, y2);
    atomicAdd(&g_z.hist[srt >> 16], 1u);
}

// ---------------- K2: suffix table + threshold (1024 threads) ----------------
__global__ void __launch_bounds__(1024) k_thresh() {
    __shared__ unsigned int part[256][4];
    __shared__ unsigned int s[256];
    __shared__ unsigned int S2[256];
    __shared__ int gsel;
    __shared__ unsigned int above_s;
    int t = threadIdx.x;
    int g = t >> 2, q = t & 3;
    const uint4* h4 = (const uint4*)g_z.hist;

    {
        unsigned int sum = 0;
#pragma unroll
        for (int b = 0; b < 16; b++) {
            uint4 v = h4[g * 64 + q * 16 + b];
            sum += v.x + v.y + v.z + v.w;
        }
        part[g][q] = sum;
    }
    __syncthreads();
    if (t < 256) s[t] = part[t][0] + part[t][1] + part[t][2] + part[t][3];
    __syncthreads();
    for (int off = 1; off < 256; off <<= 1) {
        unsigned int v = 0;
        if (t < 256) v = (t + off < 256) ? s[t + off] : 0u;
        __syncthreads();
        if (t < 256) s[t] += v;
        __syncthreads();
    }
    if (t < 256) S2[t] = s[t];
    __syncthreads();

    {
        unsigned int run = (g == 255) ? 0u : S2[g + 1];
#pragma unroll
        for (int qq = 3; qq > 0; qq--) if (qq > q) run += part[g][qq];
        uint4* s4 = (uint4*)g_sfx;
#pragma unroll
        for (int b = 15; b >= 0; b--) {
            int idx4 = g * 64 + q * 16 + b;
            uint4 h = h4[idx4];
            uint4 o;
            o.w = run; run += h.w;
            o.z = run; run += h.z;
            o.y = run; run += h.y;
            o.x = run; run += h.x;
            s4[idx4] = o;
        }
    }

    if (t < 256) {
        unsigned int nxt = (t == 255) ? 0u : S2[t + 1];
        if (S2[t] >= TOPN && nxt < TOPN) { gsel = t; above_s = nxt; }
    }
    __syncthreads();
    int gg = gsel;
    unsigned int above = above_s;
    unsigned int fv = 0;
    if (t < 256) fv = g_z.hist[gg * 256 + t];
    __syncthreads();
    if (t < 256) s[t] = fv;
    __syncthreads();
    for (int off = 1; off < 256; off <<= 1) {
        unsigned int v = 0;
        if (t < 256) v = (t + off < 256) ? s[t + off] : 0u;
        __syncthreads();
        if (t < 256) s[t] += v;
        __syncthreads();
    }
    if (t < 256) {
        unsigned int nxt2 = (t == 255) ? 0u : s[t + 1];
        if (above + s[t] >= TOPN && above + nxt2 < TOPN) {
            g_thresh = (unsigned int)(gg * 256 + t);
            g_cand_count = above + s[t];
        }
    }
}

// ---------------- K3: compact candidates into bucket-ordered slots ----------------
__global__ void k_compact() {
    int t = blockIdx.x * blockDim.x + threadIdx.x;
    if (t >= NTOT) return;
    unsigned int srt = g_srt[t];
    unsigned int b = srt >> 16;
    if (b >= g_thresh) {
        int a = t / HW;
        int k = t - a * HW;
        int i_ref = k * NA + a;   // reference flatten order (tiebreak)
        unsigned long long key =
            ((unsigned long long)srt << 32) | (0xFFFFFFFFu - (unsigned int)i_ref);
        unsigned int end = g_sfx[b - 1];                 // b >= thresh >= 1
        unsigned int old = atomicSub(&g_z.hist[b], 1u);  // counts down
        unsigned int slot = end - old;                   // bucket base .. end-1
        if (slot < CAND_MAX) g_cand[slot] = key;
    }
}

// ---------------- K4 (fused): rank+scatter -> mask -> collect ----------------
// 136 co-resident blocks (one SM each), 2 software grid barriers.
// Phase A: per-candidate exact in-bucket rank, gather box, scatter to rank
//          slot; also zero d_out.
// Phase B: block b computes triangular mask tile b (64x64 IoUs).
// Phase C: block 0 runs the serial greedy collect (identical logic to R14),
//          with in-kernel slow-path continuation beyond RTOP (rarely fires).
__global__ void __launch_bounds__(FTH) k_nms(float* __restrict__ out) {
    __shared__ float4 bb[64];
    __shared__ float ar[64];
    __shared__ unsigned long long remv[RW];
    __shared__ int klist[POSTN];
    __shared__ float4 kbox[POSTN];
    __shared__ unsigned long long tiles[2][64 * RW];   // 16 KB
    const int tid = threadIdx.x;
    const int bid = blockIdx.x;

    // ================= Phase A: rank + scatter + out-zero =================
    {
        int gtid = bid * FTH + tid;
        if (gtid < POSTN * 5) out[gtid] = 0.f;          // d_out is poisoned
        unsigned int C = g_cand_count;
        if (C > CAND_MAX) C = CAND_MAX;
        if (gtid < (int)C) {
            unsigned long long mykey = g_cand[gtid];
            unsigned int b = (unsigned int)(mykey >> 48);
            unsigned int idx = 0xFFFFFFFFu - (unsigned int)(mykey & 0xFFFFFFFFull);
            int a = idx % NA;
            int k = idx / NA;
            float4 box = g_boxes[a * HW + k];
            unsigned int base = g_sfx[b];
            unsigned int end = g_sfx[b - 1];
            if (end > C) end = C;
            unsigned int rank = base;
            for (unsigned int j = base; j < end; j++)
                rank += (g_cand[j] > mykey) ? 1u : 0u;
            if (rank < TOPN) {
                g_top_boxes[rank] = box;
                bool vkey = ((unsigned int)(mykey >> 32)) > 0x007FFFFFu;
                if (!vkey) atomicOr(&g_z.sup[rank >> 6], 1ull << (rank & 63));
            }
        }
    }
    grid_bar();

    // ================= Phase B: mask tile bid (threads < 64) =================
    {
        // triangular decode: row bi has RT-bi tiles
        int bi = 0, rem = bid;
        while (rem >= RT - bi) { rem -= RT - bi; bi++; }
        int bj = bi + rem;
        if (tid < 64) {
            int t = tid;
            int i = bi * 64 + t;
            int jg0 = bj * 64 + t;
            float4 b0 = g_top_boxes[jg0];
            bb[t] = b0;
            ar[t] = (b0.z - b0.x) * (b0.w - b0.y);
            __syncwarp();
        }
        __syncthreads();
        if (tid < 64) {
            int t = tid;
            int i = bi * 64 + t;
            float4 bi_box = g_top_boxes[i];
            float area_i = (bi_box.z - bi_box.x) * (bi_box.w - bi_box.y);
            unsigned long long m = 0ull;
#pragma unroll 4
            for (int jj = 0; jj < 64; jj++) {
                int jg = bj * 64 + jj;
                float4 bj_box = bb[jj];
                float ix1 = fmaxf(bi_box.x, bj_box.x);
                float iy1 = fmaxf(bi_box.y, bj_box.y);
                float ix2 = fminf(bi_box.z, bj_box.z);
                float iy2 = fminf(bi_box.w, bj_box.w);
                float inter = fmaxf(ix2 - ix1, 0.f) * fmaxf(iy2 - iy1, 0.f);
                float denom = fmaxf(area_i + ar[jj] - inter, 1e-9f);
                float iou = inter / denom;
                if (iou > 0.7f && jg > i) m |= (1ull << jj);
            }
            g_maskR[i * RW + bj] = m;
        }
    }
    grid_bar();

    // ================= Phase C: greedy collect (block 0 only) =================
    if (bid != 0) return;

    if (tid < RW) remv[tid] = g_z.sup[tid];
    __syncthreads();

    // prefetch tile 0 (alive rows only)
    {
        unsigned long long rv = remv[0];
        for (int t = tid; t < 64 * (RW / 2); t += FTH) {
            int r = t >> 3, c = t & 7;
            if (!((rv >> r) & 1ull))
                cp_async16(&tiles[0][r * RW + 2 * c], &g_maskR[r * RW + 2 * c]);
        }
        cp_async_commit();
    }
    cp_async_wait0();
    __syncthreads();

    int kept = 0;
    for (int ib = 0; ib < RT; ib++) {
        unsigned long long* tile = tiles[ib & 1];
        int ibe = ib & ~1;
        int off = ib - ibe;
        int wfull = RW - ibe;              // even
        if (ib + 1 < RT) {
            int nb2 = ib + 1;
            int ibe2 = nb2 & ~1;
            int wfull2 = RW - ibe2;        // even
            int half2 = wfull2 >> 1;
            unsigned long long rv = remv[nb2];
            unsigned long long* dst = tiles[nb2 & 1];
            for (int t = tid; t < 64 * half2; t += FTH) {
                int r = t / half2, c = t - r * half2;
                if (!((rv >> r) & 1ull))
                    cp_async16(&dst[r * wfull2 + 2 * c],
                               &g_maskR[(nb2 * 64 + r) * RW + ibe2 + 2 * c]);
            }
        }
        cp_async_commit();

        int wcnt = RW - ib;
        unsigned long long rcur = remv[ib];
        unsigned long long acc = 0ull;
        int w = tid;                       // owns word ib+w (0 < w < wcnt)
        while (true) {
            unsigned long long avail = ~rcur;
            if (avail == 0ull) break;
            int bit = __ffsll((long long)avail) - 1;
            if (tid == 0) klist[kept] = ib * 64 + bit;
            kept++;
            rcur |= tile[bit * wfull + off] | (1ull << bit);
            if (w > 0 && w < wcnt) acc |= tile[bit * wfull + off + w];
            if (kept >= POSTN) break;
        }
        if (w > 0 && w < wcnt) remv[ib + w] |= acc;
        if (kept >= POSTN) break;
        cp_async_wait0();
        __syncthreads();
    }
    cp_async_wait0();
    __syncthreads();

    // rare slow path: continue greedy beyond RTOP against the kept set
    if (kept < POSTN) {
        for (int t = tid; t < kept; t += FTH) kbox[t] = g_top_boxes[klist[t]];
        __syncthreads();
        for (int i = RTOP; i < TOPN && kept < POSTN; i++) {
            if ((g_z.sup[i >> 6] >> (i & 63)) & 1ull) continue;
            float4 bi = g_top_boxes[i];
            float area_i = (bi.z - bi.x) * (bi.w - bi.y);
            int sup = 0;
            for (int j = tid; j < kept; j += FTH) {
                float4 bj = kbox[j];
                float ix1 = fmaxf(bi.x, bj.x);
                float iy1 = fmaxf(bi.y, bj.y);
                float ix2 = fminf(bi.z, bj.z);
                float iy2 = fminf(bi.w, bj.w);
                float inter = fmaxf(ix2 - ix1, 0.f) * fmaxf(iy2 - iy1, 0.f);
                float area_j = (bj.z - bj.x) * (bj.w - bj.y);
                float denom = fmaxf(area_i + area_j - inter, 1e-9f);
                if (inter > 0.7f * denom) sup = 1;
            }
            if (__syncthreads_or(sup) == 0) {
                if (tid == 0) klist[kept] = i;
                kbox[kept] = bi;           // same value in every thread
                kept++;
            }
        }
        __syncthreads();
    }

    for (int t = tid; t < kept; t += FTH) {
        int idx = klist[t];
        float4 b = g_top_boxes[idx];
        float* row = out + t * 5;
        row[0] = 0.f; row[1] = b.x; row[2] = b.y; row[3] = b.z; row[4] = b.w;
    }
}

extern "C" void kernel_launch(void* const* d_in, const int* in_sizes, int n_in,
                              void* d_out, int out_size) {
    const float* scores  = (const float*)d_in[0];
    const float* deltas  = (const float*)d_in[1];
    const float* im_info = (const float*)d_in[2];
    float* out = (float*)d_out;

    void* p;
    cudaGetSymbolAddress(&p, g_z);
    cudaMemsetAsync(p, 0, sizeof(ZeroBlock));

    k_score_box<<<(NTOT + 255) / 256, 256>>>(scores, deltas, im_info);
    k_thresh<<<1, 1024>>>();
    k_compact<<<(NTOT + 255) / 256, 256>>>();
    k_nms<<<NBLK, FTH>>>(out);
}

// round 16
// speedup vs baseline: 1.0718x; 1.0718x over previous
#include <cuda_runtime.h>
#include <cstdint>

#define HF 128
#define WF 192
#define NA 9
#define HW (HF*WF)               // 24576
#define NTOT (HW*NA)             // 221184
#define TOPN 6000
#define POSTN 300
#define NB 94                    // ceil(6000/64) (sup words)
#define CAND_MAX 16384
#define RTOP 1024                // early-NMS rank bound
#define RW 16                    // RTOP/64 words per row
#define RT 16                    // RTOP/64 tiles per side
#define NTILE (RT*(RT+1)/2)      // 136 triangular tiles
#define NBLK NTILE               // fused-kernel blocks (co-resident: 136 <= 148 SMs)
#define FTH 256                  // fused-kernel threads per block
#define GSTR (NBLK*FTH)          // grid stride

__constant__ float c_anchors[NA][4] = {
    {-84.f,  -40.f,  99.f,  55.f},
    {-176.f, -88.f,  191.f, 103.f},
    {-360.f, -184.f, 375.f, 199.f},
    {-56.f,  -56.f,  71.f,  71.f},
    {-120.f, -120.f, 135.f, 135.f},
    {-248.f, -248.f, 263.f, 263.f},
    {-36.f,  -80.f,  51.f,  95.f},
    {-80.f,  -168.f, 95.f,  183.f},
    {-168.f, -344.f, 183.f, 359.f}
};

// single zeroed region (one memset node)
struct ZeroBlock {
    unsigned int hist[65536];
    unsigned long long sup[NB];
};
__device__ __align__(16) ZeroBlock g_z;

__device__ unsigned int g_srt[NTOT];                 // 32-bit sortable score
__device__ float4 g_boxes[NTOT];                     // t = a*HW + k
__device__ __align__(16) unsigned int g_sfx[65536];  // sfx[b] = #keys in buckets > b
__device__ unsigned int g_thresh;
__device__ unsigned int g_cand_count;
__device__ __align__(16) unsigned long long g_cand[CAND_MAX];
__device__ float4 g_top_boxes[TOPN];
__device__ __align__(16) unsigned long long g_maskR[RTOP * RW];   // early mask

// software grid barrier state (self-resetting across replays)
__device__ unsigned int g_bar_count;
__device__ unsigned int g_bar_gen;

// CG-style barrier: block-scope ordering via __syncthreads; gpu-scope
// release/acquire fences issued by ONE thread per block (membar drains the
// SM's whole store queue; CCTL.IVALL invalidates the whole SM's L1).
__device__ __forceinline__ void grid_bar() {
    __syncthreads();
    if (threadIdx.x == 0) {
        __threadfence();                                   // release
        unsigned int gen = atomicAdd(&g_bar_gen, 0u);
        if (atomicAdd(&g_bar_count, 1u) == NBLK - 1) {
            g_bar_count = 0;
            atomicAdd(&g_bar_gen, 1u);
        } else {
            while (atomicAdd(&g_bar_gen, 0u) == gen) { __nanosleep(64); }
        }
        __threadfence();                                   // acquire
    }
    __syncthreads();
}

__device__ __forceinline__ void cp_async16(void* smem_dst, const void* gmem_src) {
    unsigned int d = (unsigned int)__cvta_generic_to_shared(smem_dst);
    asm volatile("cp.async.cg.shared.global [%0], [%1], 16;" :: "r"(d), "l"(gmem_src) : "memory");
}
__device__ __forceinline__ void cp_async_commit() {
    asm volatile("cp.async.commit_group;" ::: "memory");
}
__device__ __forceinline__ void cp_async_wait0() {
    asm volatile("cp.async.wait_group 0;" ::: "memory");
}

// ---------------- K1: decode + boxes + sortable score + histogram ----------------
__global__ void k_score_box(const float* __restrict__ scores,
                            const float* __restrict__ deltas,
                            const float* __restrict__ im_info) {
    int t = blockIdx.x * blockDim.x + threadIdx.x;
    if (t >= NTOT) return;
    int a = t / HW;
    int k = t - a * HW;
    int xs = k >> 7;          // meshgrid 'ij' quirk: shift row k -> (x=k/128, y=k%128)
    int ys = k & 127;

    float sc = scores[(NA + a) * HW + k];
    float dx = deltas[(4*a + 0) * HW + k];
    float dy = deltas[(4*a + 1) * HW + k];
    float dw = deltas[(4*a + 2) * HW + k];
    float dh = deltas[(4*a + 3) * HW + k];

    float sx = 16.f * (float)xs;
    float sy = 16.f * (float)ys;
    float ax1 = c_anchors[a][0] + sx;
    float ay1 = c_anchors[a][1] + sy;
    float ax2 = c_anchors[a][2] + sx;
    float ay2 = c_anchors[a][3] + sy;

    float w = ax2 - ax1 + 1.f;
    float h = ay2 - ay1 + 1.f;
    float cx = ax1 + 0.5f * w;
    float cy = ay1 + 0.5f * h;

    float pcx = dx * w + cx;
    float pcy = dy * h + cy;
    float pw = expf(dw) * w;
    float ph = expf(dh) * h;

    float x1 = pcx - 0.5f * pw;
    float y1 = pcy - 0.5f * ph;
    float x2 = pcx + 0.5f * pw;
    float y2 = pcy + 0.5f * ph;

    float im0 = im_info[0], im1 = im_info[1], im2 = im_info[2];
    x1 = fminf(fmaxf(x1, 0.f), im1 - 1.f);
    x2 = fminf(fmaxf(x2, 0.f), im1 - 1.f);
    y1 = fminf(fmaxf(y1, 0.f), im0 - 1.f);
    y2 = fminf(fmaxf(y2, 0.f), im0 - 1.f);

    float ms = 16.f * im2;
    bool valid = (x2 - x1 + 1.f >= ms) && (y2 - y1 + 1.f >= ms);

    unsigned int srt;
    if (valid) {
        unsigned int b = __float_as_uint(sc);
        srt = (b & 0x80000000u) ? ~b : (b | 0x80000000u);
    } else {
        srt = 0x007FFFFFu;   // flip(-inf)
    }
    g_srt[t] = srt;
    g_boxes[t] = make_float4(x1, y1, x2, y2);
    atomicAdd(&g_z.hist[srt >> 16], 1u);
}

// ---------------- K2: suffix table + threshold (1024 threads) ----------------
__global__ void __launch_bounds__(1024) k_thresh() {
    __shared__ unsigned int part[256][4];
    __shared__ unsigned int s[256];
    __shared__ unsigned int S2[256];
    __shared__ int gsel;
    __shared__ unsigned int above_s;
    int t = threadIdx.x;
    int g = t >> 2, q = t & 3;
    const uint4* h4 = (const uint4*)g_z.hist;

    {
        unsigned int sum = 0;
#pragma unroll
        for (int b = 0; b < 16; b++) {
            uint4 v = h4[g * 64 + q * 16 + b];
            sum += v.x + v.y + v.z + v.w;
        }
        part[g][q] = sum;
    }
    __syncthreads();
    if (t < 256) s[t] = part[t][0] + part[t][1] + part[t][2] + part[t][3];
    __syncthreads();
    for (int off = 1; off < 256; off <<= 1) {
        unsigned int v = 0;
        if (t < 256) v = (t + off < 256) ? s[t + off] : 0u;
        __syncthreads();
        if (t < 256) s[t] += v;
        __syncthreads();
    }
    if (t < 256) S2[t] = s[t];
    __syncthreads();

    {
        unsigned int run = (g == 255) ? 0u : S2[g + 1];
#pragma unroll
        for (int qq = 3; qq > 0; qq--) if (qq > q) run += part[g][qq];
        uint4* s4 = (uint4*)g_sfx;
#pragma unroll
        for (int b = 15; b >= 0; b--) {
            int idx4 = g * 64 + q * 16 + b;
            uint4 h = h4[idx4];
            uint4 o;
            o.w = run; run += h.w;
            o.z = run; run += h.z;
            o.y = run; run += h.y;
            o.x = run; run += h.x;
            s4[idx4] = o;
        }
    }

    if (t < 256) {
        unsigned int nxt = (t == 255) ? 0u : S2[t + 1];
        if (S2[t] >= TOPN && nxt < TOPN) { gsel = t; above_s = nxt; }
    }
    __syncthreads();
    int gg = gsel;
    unsigned int above = above_s;
    unsigned int fv = 0;
    if (t < 256) fv = g_z.hist[gg * 256 + t];
    __syncthreads();
    if (t < 256) s[t] = fv;
    __syncthreads();
    for (int off = 1; off < 256; off <<= 1) {
        unsigned int v = 0;
        if (t < 256) v = (t + off < 256) ? s[t + off] : 0u;
        __syncthreads();
        if (t < 256) s[t] += v;
        __syncthreads();
    }
    if (t < 256) {
        unsigned int nxt2 = (t == 255) ? 0u : s[t + 1];
        if (above + s[t] >= TOPN && above + nxt2 < TOPN) {
            g_thresh = (unsigned int)(gg * 256 + t);
            g_cand_count = above + s[t];
        }
    }
}

// ---------------- K3 (fused): compact -> rank+scatter -> mask -> collect ------
// 136 co-resident blocks (one SM each), 3 cheap grid barriers.
__global__ void __launch_bounds__(FTH) k_nms(float* __restrict__ out) {
    __shared__ float4 bb[64];
    __shared__ float ar[64];
    __shared__ unsigned long long pm[4][64];           // phase-B partial masks
    __shared__ unsigned long long remv[RW];
    __shared__ int klist[POSTN];
    __shared__ float4 kbox[POSTN];
    __shared__ unsigned long long tiles[2][64 * RW];   // 16 KB
    const int tid = threadIdx.x;
    const int bid = blockIdx.x;

    // ================= Phase 0: compact (grid-stride) =================
    {
        unsigned int thr = g_thresh;
        for (int t = bid * FTH + tid; t < NTOT; t += GSTR) {
            unsigned int srt = g_srt[t];
            unsigned int b = srt >> 16;
            if (b >= thr) {
                int a = t / HW;
                int k = t - a * HW;
                int i_ref = k * NA + a;   // reference flatten order (tiebreak)
                unsigned long long key =
                    ((unsigned long long)srt << 32) | (0xFFFFFFFFu - (unsigned int)i_ref);
                unsigned int end = g_sfx[b - 1];                 // b >= thresh >= 1
                unsigned int old = atomicSub(&g_z.hist[b], 1u);  // counts down
                unsigned int slot = end - old;                   // bucket base..end-1
                if (slot < CAND_MAX) g_cand[slot] = key;
            }
        }
    }
    grid_bar();

    // ================= Phase A: rank + scatter + out-zero =================
    {
        int gtid = bid * FTH + tid;
        if (gtid < POSTN * 5) out[gtid] = 0.f;          // d_out is poisoned
        unsigned int C = g_cand_count;
        if (C > CAND_MAX) C = CAND_MAX;
        if (gtid < (int)C) {
            unsigned long long mykey = g_cand[gtid];
            unsigned int b = (unsigned int)(mykey >> 48);
            unsigned int idx = 0xFFFFFFFFu - (unsigned int)(mykey & 0xFFFFFFFFull);
            int a = idx % NA;
            int k = idx / NA;
            float4 box = g_boxes[a * HW + k];
            unsigned int base = g_sfx[b];
            unsigned int end = g_sfx[b - 1];
            if (end > C) end = C;
            unsigned int rank = base;
            for (unsigned int j = base; j < end; j++)
                rank += (g_cand[j] > mykey) ? 1u : 0u;
            if (rank < TOPN) {
                g_top_boxes[rank] = box;
                bool vkey = ((unsigned int)(mykey >> 32)) > 0x007FFFFFu;
                if (!vkey) atomicOr(&g_z.sup[rank >> 6], 1ull << (rank & 63));
            }
        }
    }
    grid_bar();

    // ================= Phase B: mask tile bid (all 256 threads) =================
    {
        int bi = 0, rem = bid;
        while (rem >= RT - bi) { rem -= RT - bi; bi++; }
        int bj = bi + rem;
        int row = tid & 63;                // 0..63
        int qq = tid >> 6;                 // 0..3 quarter of jj range
        if (tid < 64) {
            int jg0 = bj * 64 + tid;
            float4 b0 = g_top_boxes[jg0];
            bb[tid] = b0;
            ar[tid] = (b0.z - b0.x) * (b0.w - b0.y);
        }
        __syncthreads();
        {
            int i = bi * 64 + row;
            float4 bi_box = g_top_boxes[i];
            float area_i = (bi_box.z - bi_box.x) * (bi_box.w - bi_box.y);
            unsigned long long m = 0ull;
#pragma unroll
            for (int jj = qq * 16; jj < qq * 16 + 16; jj++) {
                int jg = bj * 64 + jj;
                float4 bj_box = bb[jj];
                float ix1 = fmaxf(bi_box.x, bj_box.x);
                float iy1 = fmaxf(bi_box.y, bj_box.y);
                float ix2 = fminf(bi_box.z, bj_box.z);
                float iy2 = fminf(bi_box.w, bj_box.w);
                float inter = fmaxf(ix2 - ix1, 0.f) * fmaxf(iy2 - iy1, 0.f);
                float denom = fmaxf(area_i + ar[jj] - inter, 1e-9f);
                float iou = inter / denom;
                if (iou > 0.7f && jg > i) m |= (1ull << jj);
            }
            pm[qq][row] = m;
        }
        __syncthreads();
        if (tid < 64) {
            int i = bi * 64 + tid;
            g_maskR[i * RW + bj] = pm[0][tid] | pm[1][tid] | pm[2][tid] | pm[3][tid];
        }
    }
    grid_bar();

    // ================= Phase C: greedy collect (block 0 only) =================
    if (bid != 0) return;

    if (tid < RW) remv[tid] = g_z.sup[tid];
    __syncthreads();

    // prefetch tile 0 (alive rows only)
    {
        unsigned long long rv = remv[0];
        for (int t = tid; t < 64 * (RW / 2); t += FTH) {
            int r = t >> 3, c = t & 7;
            if (!((rv >> r) & 1ull))
                cp_async16(&tiles[0][r * RW + 2 * c], &g_maskR[r * RW + 2 * c]);
        }
        cp_async_commit();
    }
    cp_async_wait0();
    __syncthreads();

    int kept = 0;
    for (int ib = 0; ib < RT; ib++) {
        unsigned long long* tile = tiles[ib & 1];
        int ibe = ib & ~1;
        int off = ib - ibe;
        int wfull = RW - ibe;              // even
        if (ib + 1 < RT) {
            int nb2 = ib + 1;
            int ibe2 = nb2 & ~1;
            int wfull2 = RW - ibe2;        // even
            int half2 = wfull2 >> 1;
            unsigned long long rv = remv[nb2];
            unsigned long long* dst = tiles[nb2 & 1];
            for (int t = tid; t < 64 * half2; t += FTH) {
                int r = t / half2, c = t - r * half2;
                if (!((rv >> r) & 1ull))
                    cp_async16(&dst[r * wfull2 + 2 * c],
                               &g_maskR[(nb2 * 64 + r) * RW + ibe2 + 2 * c]);
            }
        }
        cp_async_commit();

        int wcnt = RW - ib;
        unsigned long long rcur = remv[ib];
        unsigned long long acc = 0ull;
        int w = tid;                       // owns word ib+w (0 < w < wcnt)
        while (true) {
            unsigned long long avail = ~rcur;
            if (avail == 0ull) break;
            int bit = __ffsll((long long)avail) - 1;
            if (tid == 0) klist[kept] = ib * 64 + bit;
            kept++;
            rcur |= tile[bit * wfull + off] | (1ull << bit);
            if (w > 0 && w < wcnt) acc |= tile[bit * wfull + off + w];
            if (kept >= POSTN) break;
        }
        if (w > 0 && w < wcnt) remv[ib + w] |= acc;
        if (kept >= POSTN) break;
        cp_async_wait0();
        __syncthreads();
    }
    cp_async_wait0();
    __syncthreads();

    // rare slow path: continue greedy beyond RTOP against the kept set
    if (kept < POSTN) {
        for (int t = tid; t < kept; t += FTH) kbox[t] = g_top_boxes[klist[t]];
        __syncthreads();
        for (int i = RTOP; i < TOPN && kept < POSTN; i++) {
            if ((g_z.sup[i >> 6] >> (i & 63)) & 1ull) continue;
            float4 bi = g_top_boxes[i];
            float area_i = (bi.z - bi.x) * (bi.w - bi.y);
            int sup = 0;
            for (int j = tid; j < kept; j += FTH) {
                float4 bj = kbox[j];
                float ix1 = fmaxf(bi.x, bj.x);
                float iy1 = fmaxf(bi.y, bj.y);
                float ix2 = fminf(bi.z, bj.z);
                float iy2 = fminf(bi.w, bj.w);
                float inter = fmaxf(ix2 - ix1, 0.f) * fmaxf(iy2 - iy1, 0.f);
                float area_j = (bj.z - bj.x) * (bj.w - bj.y);
                float denom = fmaxf(area_i + area_j - inter, 1e-9f);
                if (inter > 0.7f * denom) sup = 1;
            }
            if (__syncthreads_or(sup) == 0) {
                if (tid == 0) klist[kept] = i;
                kbox[kept] = bi;           // same value in every thread
                kept++;
            }
        }
        __syncthreads();
    }

    for (int t = tid; t < kept; t += FTH) {
        int idx = klist[t];
        float4 b = g_top_boxes[idx];
        float* row = out + t * 5;
        row[0] = 0.f; row[1] = b.x; row[2] = b.y; row[3] = b.z; row[4] = b.w;
    }
}

extern "C" void kernel_launch(void* const* d_in, const int* in_sizes, int n_in,
                              void* d_out, int out_size) {
    const float* scores  = (const float*)d_in[0];
    const float* deltas  = (const float*)d_in[1];
    const float* im_info = (const float*)d_in[2];
    float* out = (float*)d_out;

    void* p;
    cudaGetSymbolAddress(&p, g_z);
    cudaMemsetAsync(p, 0, sizeof(ZeroBlock));

    k_score_box<<<(NTOT + 255) / 256, 256>>>(scores, deltas, im_info);
    k_thresh<<<1, 1024>>>();
    k_nms<<<NBLK, FTH>>>(out);
}

// round 17
// speedup vs baseline: 1.0778x; 1.0056x over previous
#include <cuda_runtime.h>
#include <cstdint>

#define HF 128
#define WF 192
#define NA 9
#define HW (HF*WF)               // 24576
#define NTOT (HW*NA)             // 221184
#define TOPN 6000
#define POSTN 300
#define NB 94                    // ceil(6000/64) (sup words)
#define CAND_MAX 16384
#define RTOP 1024                // early-NMS rank bound
#define RW 16                    // RTOP/64 words per row
#define RT 16                    // RTOP/64 tiles per side
#define NTILE (RT*(RT+1)/2)      // 136 triangular tiles
#define NBLK NTILE               // fused-kernel blocks (co-resident: 136 <= 148 SMs)
#define FTH 256                  // fused-kernel threads per block
#define GSTR (NBLK*FTH)          // grid stride

__constant__ float c_anchors[NA][4] = {
    {-84.f,  -40.f,  99.f,  55.f},
    {-176.f, -88.f,  191.f, 103.f},
    {-360.f, -184.f, 375.f, 199.f},
    {-56.f,  -56.f,  71.f,  71.f},
    {-120.f, -120.f, 135.f, 135.f},
    {-248.f, -248.f, 263.f, 263.f},
    {-36.f,  -80.f,  51.f,  95.f},
    {-80.f,  -168.f, 95.f,  183.f},
    {-168.f, -344.f, 183.f, 359.f}
};

// single zeroed region (one memset node)
struct ZeroBlock {
    unsigned int hist[65536];
    unsigned long long sup[NB];
};
__device__ __align__(16) ZeroBlock g_z;

__device__ __align__(16) unsigned int g_srt[NTOT];   // 32-bit sortable score
__device__ __align__(16) unsigned int g_sfx[65536];  // sfx[b] = #keys in buckets > b
__device__ unsigned int g_thresh;
__device__ unsigned int g_cand_count;
__device__ __align__(16) unsigned long long g_cand[CAND_MAX];
__device__ float4 g_top_boxes[TOPN];
__device__ __align__(16) unsigned long long g_maskR[RTOP * RW];   // early mask

// software grid barrier state (self-resetting across replays)
__device__ unsigned int g_bar_count;
__device__ unsigned int g_bar_gen;

// CG-style barrier: block-scope ordering via __syncthreads; gpu-scope
// release/acquire fences issued by ONE thread per block.
__device__ __forceinline__ void grid_bar() {
    __syncthreads();
    if (threadIdx.x == 0) {
        __threadfence();                                   // release
        unsigned int gen = atomicAdd(&g_bar_gen, 0u);
        if (atomicAdd(&g_bar_count, 1u) == NBLK - 1) {
            g_bar_count = 0;
            atomicAdd(&g_bar_gen, 1u);
        } else {
            while (atomicAdd(&g_bar_gen, 0u) == gen) { __nanosleep(64); }
        }
        __threadfence();                                   // acquire
    }
    __syncthreads();
}

__device__ __forceinline__ void cp_async16(void* smem_dst, const void* gmem_src) {
    unsigned int d = (unsigned int)__cvta_generic_to_shared(smem_dst);
    asm volatile("cp.async.cg.shared.global [%0], [%1], 16;" :: "r"(d), "l"(gmem_src) : "memory");
}
__device__ __forceinline__ void cp_async_commit() {
    asm volatile("cp.async.commit_group;" ::: "memory");
}
__device__ __forceinline__ void cp_async_wait0() {
    asm volatile("cp.async.wait_group 0;" ::: "memory");
}

// decode one anchor box; returns box, sets *valid
__device__ __forceinline__ float4 decode_box(int a, int k,
                                             float dx, float dy, float dw, float dh,
                                             float im0, float im1, float im2,
                                             bool* valid) {
    int xs = k >> 7;          // meshgrid 'ij' quirk: shift row k -> (x=k/128, y=k%128)
    int ys = k & 127;
    float sx = 16.f * (float)xs;
    float sy = 16.f * (float)ys;
    float ax1 = c_anchors[a][0] + sx;
    float ay1 = c_anchors[a][1] + sy;
    float ax2 = c_anchors[a][2] + sx;
    float ay2 = c_anchors[a][3] + sy;

    float w = ax2 - ax1 + 1.f;
    float h = ay2 - ay1 + 1.f;
    float cx = ax1 + 0.5f * w;
    float cy = ay1 + 0.5f * h;

    float pcx = dx * w + cx;
    float pcy = dy * h + cy;
    float pw = expf(dw) * w;
    float ph = expf(dh) * h;

    float x1 = pcx - 0.5f * pw;
    float y1 = pcy - 0.5f * ph;
    float x2 = pcx + 0.5f * pw;
    float y2 = pcy + 0.5f * ph;

    x1 = fminf(fmaxf(x1, 0.f), im1 - 1.f);
    x2 = fminf(fmaxf(x2, 0.f), im1 - 1.f);
    y1 = fminf(fmaxf(y1, 0.f), im0 - 1.f);
    y2 = fminf(fmaxf(y2, 0.f), im0 - 1.f);

    float ms = 16.f * im2;
    *valid = (x2 - x1 + 1.f >= ms) && (y2 - y1 + 1.f >= ms);
    return make_float4(x1, y1, x2, y2);
}

__device__ __forceinline__ unsigned int srt_of(float sc, bool valid) {
    if (valid) {
        unsigned int b = __float_as_uint(sc);
        return (b & 0x80000000u) ? ~b : (b | 0x80000000u);
    }
    return 0x007FFFFFu;   // flip(-inf)
}

// ---------------- K1: sortable scores + histogram (4x vectorized) ----------------
__global__ void k_score_box(const float* __restrict__ scores,
                            const float* __restrict__ deltas,
                            const float* __restrict__ im_info) {
    const int HW4 = HW / 4;
    int t4 = blockIdx.x * blockDim.x + threadIdx.x;
    if (t4 >= NTOT / 4) return;
    int a = t4 / HW4;
    int q = t4 - a * HW4;        // float4 index within plane
    int k0 = q * 4;

    float4 sc = ((const float4*)(scores + (NA + a) * HW))[q];
    float4 dx = ((const float4*)(deltas + (4*a + 0) * HW))[q];
    float4 dy = ((const float4*)(deltas + (4*a + 1) * HW))[q];
    float4 dw = ((const float4*)(deltas + (4*a + 2) * HW))[q];
    float4 dh = ((const float4*)(deltas + (4*a + 3) * HW))[q];
    float im0 = im_info[0], im1 = im_info[1], im2 = im_info[2];

    bool v0, v1, v2, v3;
    decode_box(a, k0 + 0, dx.x, dy.x, dw.x, dh.x, im0, im1, im2, &v0);
    decode_box(a, k0 + 1, dx.y, dy.y, dw.y, dh.y, im0, im1, im2, &v1);
    decode_box(a, k0 + 2, dx.z, dy.z, dw.z, dh.z, im0, im1, im2, &v2);
    decode_box(a, k0 + 3, dx.w, dy.w, dw.w, dh.w, im0, im1, im2, &v3);

    uint4 o;
    o.x = srt_of(sc.x, v0);
    o.y = srt_of(sc.y, v1);
    o.z = srt_of(sc.z, v2);
    o.w = srt_of(sc.w, v3);
    ((uint4*)(g_srt + a * HW))[q] = o;

    atomicAdd(&g_z.hist[o.x >> 16], 1u);
    atomicAdd(&g_z.hist[o.y >> 16], 1u);
    atomicAdd(&g_z.hist[o.z >> 16], 1u);
    atomicAdd(&g_z.hist[o.w >> 16], 1u);
}

// ---------------- K2: suffix table + threshold (1024 threads) ----------------
__global__ void __launch_bounds__(1024) k_thresh() {
    __shared__ unsigned int part[256][4];
    __shared__ unsigned int s[256];
    __shared__ unsigned int S2[256];
    __shared__ int gsel;
    __shared__ unsigned int above_s;
    int t = threadIdx.x;
    int g = t >> 2, q = t & 3;
    const uint4* h4 = (const uint4*)g_z.hist;

    {
        unsigned int sum = 0;
#pragma unroll
        for (int b = 0; b < 16; b++) {
            uint4 v = h4[g * 64 + q * 16 + b];
            sum += v.x + v.y + v.z + v.w;
        }
        part[g][q] = sum;
    }
    __syncthreads();
    if (t < 256) s[t] = part[t][0] + part[t][1] + part[t][2] + part[t][3];
    __syncthreads();
    for (int off = 1; off < 256; off <<= 1) {
        unsigned int v = 0;
        if (t < 256) v = (t + off < 256) ? s[t + off] : 0u;
        __syncthreads();
        if (t < 256) s[t] += v;
        __syncthreads();
    }
    if (t < 256) S2[t] = s[t];
    __syncthreads();

    {
        unsigned int run = (g == 255) ? 0u : S2[g + 1];
#pragma unroll
        for (int qq = 3; qq > 0; qq--) if (qq > q) run += part[g][qq];
        uint4* s4 = (uint4*)g_sfx;
#pragma unroll
        for (int b = 15; b >= 0; b--) {
            int idx4 = g * 64 + q * 16 + b;
            uint4 h = h4[idx4];
            uint4 o;
            o.w = run; run += h.w;
            o.z = run; run += h.z;
            o.y = run; run += h.y;
            o.x = run; run += h.x;
            s4[idx4] = o;
        }
    }

    if (t < 256) {
        unsigned int nxt = (t == 255) ? 0u : S2[t + 1];
        if (S2[t] >= TOPN && nxt < TOPN) { gsel = t; above_s = nxt; }
    }
    __syncthreads();
    int gg = gsel;
    unsigned int above = above_s;
    unsigned int fv = 0;
    if (t < 256) fv = g_z.hist[gg * 256 + t];
    __syncthreads();
    if (t < 256) s[t] = fv;
    __syncthreads();
    for (int off = 1; off < 256; off <<= 1) {
        unsigned int v = 0;
        if (t < 256) v = (t + off < 256) ? s[t + off] : 0u;
        __syncthreads();
        if (t < 256) s[t] += v;
        __syncthreads();
    }
    if (t < 256) {
        unsigned int nxt2 = (t == 255) ? 0u : s[t + 1];
        if (above + s[t] >= TOPN && above + nxt2 < TOPN) {
            g_thresh = (unsigned int)(gg * 256 + t);
            g_cand_count = above + s[t];
        }
    }
}

// ---------------- K3 (fused): compact -> rank+decode+scatter -> mask -> collect --
__global__ void __launch_bounds__(FTH) k_nms(const float* __restrict__ deltas,
                                             const float* __restrict__ im_info,
                                             float* __restrict__ out) {
    __shared__ float4 bb[64];
    __shared__ float ar[64];
    __shared__ unsigned long long pm[4][64];           // phase-B partial masks
    __shared__ unsigned long long remv[RW];
    __shared__ int klist[POSTN];
    __shared__ float4 kbox[POSTN];
    __shared__ unsigned long long tiles[2][64 * RW];   // 16 KB
    const int tid = threadIdx.x;
    const int bid = blockIdx.x;

    // ================= Phase 0: compact (grid-stride) =================
    {
        unsigned int thr = g_thresh;
        for (int t = bid * FTH + tid; t < NTOT; t += GSTR) {
            unsigned int srt = g_srt[t];
            unsigned int b = srt >> 16;
            if (b >= thr) {
                int a = t / HW;
                int k = t - a * HW;
                int i_ref = k * NA + a;   // reference flatten order (tiebreak)
                unsigned long long key =
                    ((unsigned long long)srt << 32) | (0xFFFFFFFFu - (unsigned int)i_ref);
                unsigned int end = g_sfx[b - 1];                 // b >= thresh >= 1
                unsigned int old = atomicSub(&g_z.hist[b], 1u);  // counts down
                unsigned int slot = end - old;                   // bucket base..end-1
                if (slot < CAND_MAX) g_cand[slot] = key;
            }
        }
    }
    grid_bar();

    // ================= Phase A: rank + decode + scatter + out-zero =================
    {
        int gtid = bid * FTH + tid;
        if (gtid < POSTN * 5) out[gtid] = 0.f;          // d_out is poisoned
        unsigned int C = g_cand_count;
        if (C > CAND_MAX) C = CAND_MAX;
        if (gtid < (int)C) {
            unsigned long long mykey = g_cand[gtid];
            unsigned int b = (unsigned int)(mykey >> 48);
            unsigned int idx = 0xFFFFFFFFu - (unsigned int)(mykey & 0xFFFFFFFFull);
            int a = idx % NA;
            int k = idx / NA;
            // hoist decode inputs ahead of the rank loop
            float dx = __ldg(&deltas[(4*a + 0) * HW + k]);
            float dy = __ldg(&deltas[(4*a + 1) * HW + k]);
            float dw = __ldg(&deltas[(4*a + 2) * HW + k]);
            float dh = __ldg(&deltas[(4*a + 3) * HW + k]);
            float im0 = __ldg(&im_info[0]), im1 = __ldg(&im_info[1]), im2 = __ldg(&im_info[2]);
            unsigned int base = g_sfx[b];
            unsigned int end = g_sfx[b - 1];
            if (end > C) end = C;
            unsigned int rank = base;
            for (unsigned int j = base; j < end; j++)
                rank += (g_cand[j] > mykey) ? 1u : 0u;
            if (rank < TOPN) {
                bool valid;
                float4 box = decode_box(a, k, dx, dy, dw, dh, im0, im1, im2, &valid);
                g_top_boxes[rank] = box;
                bool vkey = ((unsigned int)(mykey >> 32)) > 0x007FFFFFu;
                if (!vkey) atomicOr(&g_z.sup[rank >> 6], 1ull << (rank & 63));
            }
        }
    }
    grid_bar();

    // ================= Phase B: mask tile bid (all 256 threads) =================
    {
        int bi = 0, rem = bid;
        while (rem >= RT - bi) { rem -= RT - bi; bi++; }
        int bj = bi + rem;
        int row = tid & 63;                // 0..63
        int qq = tid >> 6;                 // 0..3 quarter of jj range
        if (tid < 64) {
            int jg0 = bj * 64 + tid;
            float4 b0 = g_top_boxes[jg0];
            bb[tid] = b0;
            ar[tid] = (b0.z - b0.x) * (b0.w - b0.y);
        }
        __syncthreads();
        {
            int i = bi * 64 + row;
            float4 bi_box = g_top_boxes[i];
            float area_i = (bi_box.z - bi_box.x) * (bi_box.w - bi_box.y);
            unsigned long long m = 0ull;
#pragma unroll
            for (int jj = qq * 16; jj < qq * 16 + 16; jj++) {
                int jg = bj * 64 + jj;
                float4 bj_box = bb[jj];
                float ix1 = fmaxf(bi_box.x, bj_box.x);
                float iy1 = fmaxf(bi_box.y, bj_box.y);
                float ix2 = fminf(bi_box.z, bj_box.z);
                float iy2 = fminf(bi_box.w, bj_box.w);
                float inter = fmaxf(ix2 - ix1, 0.f) * fmaxf(iy2 - iy1, 0.f);
                float denom = fmaxf(area_i + ar[jj] - inter, 1e-9f);
                float iou = inter / denom;
                if (iou > 0.7f && jg > i) m |= (1ull << jj);
            }
            pm[qq][row] = m;
        }
        __syncthreads();
        if (tid < 64) {
            int i = bi * 64 + tid;
            g_maskR[i * RW + bj] = pm[0][tid] | pm[1][tid] | pm[2][tid] | pm[3][tid];
        }
    }
    grid_bar();

    // ================= Phase C: greedy collect (block 0 only) =================
    if (bid != 0) return;

    if (tid < RW) remv[tid] = g_z.sup[tid];
    __syncthreads();

    // prefetch tile 0 (alive rows only)
    {
        unsigned long long rv = remv[0];
        for (int t = tid; t < 64 * (RW / 2); t += FTH) {
            int r = t >> 3, c = t & 7;
            if (!((rv >> r) & 1ull))
                cp_async16(&tiles[0][r * RW + 2 * c], &g_maskR[r * RW + 2 * c]);
        }
        cp_async_commit();
    }
    cp_async_wait0();
    __syncthreads();

    int kept = 0;
    for (int ib = 0; ib < RT; ib++) {
        unsigned long long* tile = tiles[ib & 1];
        int ibe = ib & ~1;
        int off = ib - ibe;
        int wfull = RW - ibe;              // even
        if (ib + 1 < RT) {
            int nb2 = ib + 1;
            int ibe2 = nb2 & ~1;
            int wfull2 = RW - ibe2;        // even
            int half2 = wfull2 >> 1;
            unsigned long long rv = remv[nb2];
            unsigned long long* dst = tiles[nb2 & 1];
            for (int t = tid; t < 64 * half2; t += FTH) {
                int r = t / half2, c = t - r * half2;
                if (!((rv >> r) & 1ull))
                    cp_async16(&dst[r * wfull2 + 2 * c],
                               &g_maskR[(nb2 * 64 + r) * RW + ibe2 + 2 * c]);
            }
        }
        cp_async_commit();

        int wcnt = RW - ib;
        unsigned long long rcur = remv[ib];
        unsigned long long acc = 0ull;
        int w = tid;                       // owns word ib+w (0 < w < wcnt)
        while (true) {
            unsigned long long avail = ~rcur;
            if (avail == 0ull) break;
            int bit = __ffsll((long long)avail) - 1;
            if (tid == 0) klist[kept] = ib * 64 + bit;
            kept++;
            rcur |= tile[bit * wfull + off] | (1ull << bit);
            if (w > 0 && w < wcnt) acc |= tile[bit * wfull + off + w];
            if (kept >= POSTN) break;
        }
        if (w > 0 && w < wcnt) remv[ib + w] |= acc;
        if (kept >= POSTN) break;
        cp_async_wait0();
        __syncthreads();
    }
    cp_async_wait0();
    __syncthreads();

    // rare slow path: continue greedy beyond RTOP against the kept set
    if (kept < POSTN) {
        for (int t = tid; t < kept; t += FTH) kbox[t] = g_top_boxes[klist[t]];
        __syncthreads();
        for (int i = RTOP; i < TOPN && kept < POSTN; i++) {
            if ((g_z.sup[i >> 6] >> (i & 63)) & 1ull) continue;
            float4 bi = g_top_boxes[i];
            float area_i = (bi.z - bi.x) * (bi.w - bi.y);
            int sup = 0;
            for (int j = tid; j < kept; j += FTH) {
                float4 bj = kbox[j];
                float ix1 = fmaxf(bi.x, bj.x);
                float iy1 = fmaxf(bi.y, bj.y);
                float ix2 = fminf(bi.z, bj.z);
                float iy2 = fminf(bi.w, bj.w);
                float inter = fmaxf(ix2 - ix1, 0.f) * fmaxf(iy2 - iy1, 0.f);
                float area_j = (bj.z - bj.x) * (bj.w - bj.y);
                float denom = fmaxf(area_i + area_j - inter, 1e-9f);
                if (inter > 0.7f * denom) sup = 1;
            }
            if (__syncthreads_or(sup) == 0) {
                if (tid == 0) klist[kept] = i;
                kbox[kept] = bi;           // same value in every thread
                kept++;
            }
        }
        __syncthreads();
    }

    for (int t = tid; t < kept; t += FTH) {
        int idx = klist[t];
        float4 b = g_top_boxes[idx];
        float* row = out + t * 5;
        row[0] = 0.f; row[1] = b.x; row[2] = b.y; row[3] = b.z; row[4] = b.w;
    }
}

extern "C" void kernel_launch(void* const* d_in, const int* in_sizes, int n_in,
                              void* d_out, int out_size) {
    const float* scores  = (const float*)d_in[0];
    const float* deltas  = (const float*)d_in[1];
    const float* im_info = (const float*)d_in[2];
    float* out = (float*)d_out;

    void* p;
    cudaGetSymbolAddress(&p, g_z);
    cudaMemsetAsync(p, 0, sizeof(ZeroBlock));

    k_score_box<<<(NTOT / 4 + 255) / 256, 256>>>(scores, deltas, im_info);
    k_thresh<<<1, 1024>>>();
    k_nms<<<NBLK, FTH>>>(deltas, im_info, out);
}